// round 1
// baseline (speedup 1.0000x reference)
#include <cuda_runtime.h>

#define BATCH 512
#define NP1   257   // N+1 tokens
#define DP1   129   // D+1 features
#define DD    128
#define NTOK  256
#define NLAYER 4

// ---- scratch (static device globals; no allocation in kernel_launch) ----
__device__ float g_Zalt[(size_t)BATCH * NP1 * DP1];   // ping-pong partner of d_out
__device__ float g_acc [(size_t)BATCH * NP1 * DP1];   // running sum_{k<i} R_k * gamma_k
__device__ float g_G   [(size_t)BATCH * DP1 * DP1];   // per-batch Gram  Z[:256]^T Z[:256]
__device__ float g_W   [(size_t)BATCH * DP1 * DP1];   // per-batch  Q_full G P_full^T

// ---------------------------------------------------------------------------
// init: copy input Z into working buffer (d_out), zero the accumulator.
// ---------------------------------------------------------------------------
__global__ void k_init(const float* __restrict__ Z, float* __restrict__ Z0) {
    size_t i = (size_t)blockIdx.x * blockDim.x + threadIdx.x;
    size_t total = (size_t)BATCH * NP1 * DP1;
    if (i < total) {
        Z0[i]    = Z[i];
        g_acc[i] = 0.0f;
    }
}

// ---------------------------------------------------------------------------
// k_gram: per batch  G = Z[:256]^T @ Z[:256]   (129x129, K=256)
//   (the "zero last key row" mask == drop token 256 from the Gram sum)
// 256 threads as 16x16, 9x9 register tile per thread.
// ---------------------------------------------------------------------------
__global__ __launch_bounds__(256) void k_gram(const float* __restrict__ Zin) {
    int b = blockIdx.x;
    const float* Zb = Zin + (size_t)b * NP1 * DP1;
    float*       Gb = g_G + (size_t)b * DP1 * DP1;

    __shared__ float Zs[16][DP1];

    int tid = threadIdx.x;
    int tx = tid & 15, ty = tid >> 4;

    float acc[9][9];
#pragma unroll
    for (int u = 0; u < 9; u++)
#pragma unroll
        for (int v = 0; v < 9; v++) acc[u][v] = 0.0f;

    for (int k0 = 0; k0 < NTOK; k0 += 16) {
        for (int idx = tid; idx < 16 * DP1; idx += 256) {
            int r = idx / DP1, c = idx - r * DP1;
            Zs[r][c] = Zb[(size_t)(k0 + r) * DP1 + c];
        }
        __syncthreads();
#pragma unroll 4
        for (int kk = 0; kk < 16; kk++) {
            float za[9], zb[9];
#pragma unroll
            for (int u = 0; u < 9; u++) {
                int r = ty + 16 * u;
                za[u] = (r < DP1) ? Zs[kk][r] : 0.0f;
            }
#pragma unroll
            for (int v = 0; v < 9; v++) {
                int c = tx + 16 * v;
                zb[v] = (c < DP1) ? Zs[kk][c] : 0.0f;
            }
#pragma unroll
            for (int u = 0; u < 9; u++)
#pragma unroll
                for (int v = 0; v < 9; v++)
                    acc[u][v] += za[u] * zb[v];
        }
        __syncthreads();
    }

    for (int u = 0; u < 9; u++) {
        int r = ty + 16 * u;
        if (r >= DP1) continue;
        for (int v = 0; v < 9; v++) {
            int c = tx + 16 * v;
            if (c >= DP1) continue;
            Gb[r * DP1 + c] = acc[u][v];
        }
    }
}

// ---------------------------------------------------------------------------
// k_pqw: per batch  W = Q_full @ (G @ P_full^T)
//   S[i, j<128] = sum_{k<128} G[i,k] P[j,k] ;  S[i,128] = G[i,128]
//   W[i<128, j] = sum_{k<128} Q[i,k] S[k,j] ;  W[128, j] = 0
// G and S staged in dynamic shared memory (2 * 129*129 * 4B = 133 KB).
// ---------------------------------------------------------------------------
extern __shared__ float sm_pqw[];

__global__ __launch_bounds__(256) void k_pqw(const float* __restrict__ P,
                                             const float* __restrict__ Q) {
    int b = blockIdx.x;
    const float* Gb = g_G + (size_t)b * DP1 * DP1;
    float*       Wb = g_W + (size_t)b * DP1 * DP1;

    float* Gs = sm_pqw;
    float* Ss = sm_pqw + DP1 * DP1;

    int tid = threadIdx.x;
    int tx = tid & 15, ty = tid >> 4;

    for (int idx = tid; idx < DP1 * DP1; idx += 256) Gs[idx] = Gb[idx];
    __syncthreads();

    // stage 1: S = G @ P_full^T
    {
        float acc[9][9];
#pragma unroll
        for (int u = 0; u < 9; u++)
#pragma unroll
            for (int v = 0; v < 9; v++) acc[u][v] = 0.0f;

        for (int k = 0; k < DD; k++) {
            float gi[9], pj[9];
#pragma unroll
            for (int u = 0; u < 9; u++) {
                int i = ty + 16 * u;
                gi[u] = (i < DP1) ? Gs[i * DP1 + k] : 0.0f;
            }
#pragma unroll
            for (int v = 0; v < 9; v++) {
                int j = tx + 16 * v;
                pj[v] = (j < DD) ? P[j * DD + k] : 0.0f;
            }
#pragma unroll
            for (int u = 0; u < 9; u++)
#pragma unroll
                for (int v = 0; v < 9; v++)
                    acc[u][v] += gi[u] * pj[v];
        }

        for (int u = 0; u < 9; u++) {
            int i = ty + 16 * u;
            if (i >= DP1) continue;
            for (int v = 0; v < 9; v++) {
                int j = tx + 16 * v;
                if (j >= DP1) continue;
                Ss[i * DP1 + j] = (j == DD) ? Gs[i * DP1 + DD] : acc[u][v];
            }
        }
    }
    __syncthreads();

    // stage 2: W = Q_full @ S
    {
        float acc[9][9];
#pragma unroll
        for (int u = 0; u < 9; u++)
#pragma unroll
            for (int v = 0; v < 9; v++) acc[u][v] = 0.0f;

        for (int k = 0; k < DD; k++) {
            float qi[9], sj[9];
#pragma unroll
            for (int u = 0; u < 9; u++) {
                int i = ty + 16 * u;
                qi[u] = (i < DD) ? Q[i * DD + k] : 0.0f;
            }
#pragma unroll
            for (int v = 0; v < 9; v++) {
                int j = tx + 16 * v;
                sj[v] = (j < DP1) ? Ss[k * DP1 + j] : 0.0f;
            }
#pragma unroll
            for (int u = 0; u < 9; u++)
#pragma unroll
                for (int v = 0; v < 9; v++)
                    acc[u][v] += qi[u] * sj[v];
        }

        for (int u = 0; u < 9; u++) {
            int i = ty + 16 * u;
            if (i >= DP1) continue;
            for (int v = 0; v < 9; v++) {
                int j = tx + 16 * v;
                if (j >= DP1) continue;
                Wb[i * DP1 + j] = (i == DD) ? 0.0f : acc[u][v];
            }
        }
    }
}

// ---------------------------------------------------------------------------
// k_out: per (batch, 64-row tile):
//   R = (Z @ W) / 256 ;  Zout = Zin + R + acc ;  acc += R * gamma_layer
// Written to the ping-pong partner, so no in-place RAW hazard across CTAs.
// ---------------------------------------------------------------------------
__global__ __launch_bounds__(256) void k_out(const float* __restrict__ Zin,
                                             const float* __restrict__ gamma_l,
                                             float* __restrict__ Zout) {
    int b  = blockIdx.y;
    int n0 = blockIdx.x * 64;

    const float* Zb = Zin + (size_t)b * NP1 * DP1;
    const float* Wb = g_W + (size_t)b * DP1 * DP1;

    __shared__ float Zs[64][16];
    __shared__ float Ws[16][DP1 + 3];   // 132 stride

    int tid = threadIdx.x;
    int tx = tid & 31, ty = tid >> 5;   // 32 x 8

    float acc[8][5];
#pragma unroll
    for (int u = 0; u < 8; u++)
#pragma unroll
        for (int v = 0; v < 5; v++) acc[u][v] = 0.0f;

    for (int k0 = 0; k0 < DP1; k0 += 16) {
        int kc = DP1 - k0;
        if (kc > 16) kc = 16;

        for (int idx = tid; idx < 64 * kc; idx += 256) {
            int r = idx / kc, c = idx - r * kc;
            int n = n0 + r;
            Zs[r][c] = (n < NP1) ? Zb[(size_t)n * DP1 + k0 + c] : 0.0f;
        }
        for (int idx = tid; idx < kc * DP1; idx += 256) {
            int r = idx / DP1, c = idx - r * DP1;
            Ws[r][c] = Wb[(k0 + r) * DP1 + c];
        }
        __syncthreads();

        if (kc == 16) {
#pragma unroll 4
            for (int kk = 0; kk < 16; kk++) {
                float zr[8], wc[5];
#pragma unroll
                for (int u = 0; u < 8; u++) zr[u] = Zs[ty + 8 * u][kk];
#pragma unroll
                for (int v = 0; v < 5; v++) {
                    int d = tx + 32 * v;
                    wc[v] = (d < DP1) ? Ws[kk][d] : 0.0f;
                }
#pragma unroll
                for (int u = 0; u < 8; u++)
#pragma unroll
                    for (int v = 0; v < 5; v++)
                        acc[u][v] += zr[u] * wc[v];
            }
        } else {
            for (int kk = 0; kk < kc; kk++) {
                float zr[8], wc[5];
#pragma unroll
                for (int u = 0; u < 8; u++) zr[u] = Zs[ty + 8 * u][kk];
#pragma unroll
                for (int v = 0; v < 5; v++) {
                    int d = tx + 32 * v;
                    wc[v] = (d < DP1) ? Ws[kk][d] : 0.0f;
                }
#pragma unroll
                for (int u = 0; u < 8; u++)
#pragma unroll
                    for (int v = 0; v < 5; v++)
                        acc[u][v] += zr[u] * wc[v];
            }
        }
        __syncthreads();
    }

    const float inv = 1.0f / 256.0f;
    for (int u = 0; u < 8; u++) {
        int n = n0 + ty + 8 * u;
        if (n >= NP1) continue;
        for (int v = 0; v < 5; v++) {
            int d = tx + 32 * v;
            if (d >= DP1) continue;
            size_t idx = ((size_t)b * NP1 + n) * DP1 + d;
            float r = acc[u][v] * inv;
            float a = g_acc[idx];
            Zout[idx]  = Zin[idx] + r + a;
            g_acc[idx] = a + r * gamma_l[n * DP1 + d];
        }
    }
}

// ---------------------------------------------------------------------------
extern "C" void kernel_launch(void* const* d_in, const int* in_sizes, int n_in,
                              void* d_out, int out_size) {
    const float* Z        = (const float*)d_in[0];
    const float* allparam = (const float*)d_in[1];
    const float* gamma    = (const float*)d_in[2];

    float* Z0 = (float*)d_out;
    float* Z1 = nullptr;
    cudaGetSymbolAddress((void**)&Z1, g_Zalt);

    cudaFuncSetAttribute(k_pqw, cudaFuncAttributeMaxDynamicSharedMemorySize,
                         2 * DP1 * DP1 * (int)sizeof(float));

    size_t total = (size_t)BATCH * NP1 * DP1;
    int initBlocks = (int)((total + 255) / 256);
    k_init<<<initBlocks, 256>>>(Z, Z0);

    const float* zin = Z0;
    float* zout = Z1;
    for (int l = 0; l < NLAYER; l++) {
        const float* Pl = allparam + (size_t)(l * 2 + 0) * DD * DD;
        const float* Ql = allparam + (size_t)(l * 2 + 1) * DD * DD;

        k_gram<<<BATCH, 256>>>(zin);
        k_pqw<<<BATCH, 256, 2 * DP1 * DP1 * sizeof(float)>>>(Pl, Ql);
        k_out<<<dim3(5, BATCH), 256>>>(zin, gamma + (size_t)l * NP1 * DP1, zout);

        float* t = (float*)zin;
        zin = zout;
        zout = t;
    }
    // after 4 swaps zin == Z0 == d_out : final Z is already in place
}

// round 2
// speedup vs baseline: 3.5862x; 3.5862x over previous
#include <cuda_runtime.h>
#include <cuda_bf16.h>
#include <cstdint>

#define BATCH  512
#define NP1    257
#define DP1    129
#define NLAYER 4
#define PD     144            // padded 129 -> 144
#define ZLD    144            // bf16 Z leading dim

typedef __nv_bfloat16 bf16;

// ------------------------- device scratch (static) -------------------------
__device__ bf16  g_Zh  [(size_t)BATCH * NP1 * ZLD];   // bf16 shadow of Z, zero-padded cols
__device__ float g_Zalt[(size_t)BATCH * NP1 * DP1];   // fp32 ping-pong partner of d_out
__device__ float g_acc [(size_t)BATCH * NP1 * DP1];   // running sum R_k * gamma_k
__device__ bf16  g_G   [(size_t)BATCH * PD * PD];     // Gram (pads auto-zero)
__device__ bf16  g_W   [(size_t)BATCH * PD * PD];     // Q G P^T (pads auto-zero)
__device__ bf16  g_PQ  [NLAYER * 2 * 128 * 128];      // bf16 P,Q weights

// ------------------------------ mma helpers --------------------------------
__device__ __forceinline__ uint32_t smaddr(const void* p) {
    return (uint32_t)__cvta_generic_to_shared(p);
}
__device__ __forceinline__ void ldmx4(uint32_t* r, uint32_t a) {
    asm volatile("ldmatrix.sync.aligned.m8n8.x4.shared.b16 {%0,%1,%2,%3}, [%4];"
                 : "=r"(r[0]), "=r"(r[1]), "=r"(r[2]), "=r"(r[3]) : "r"(a));
}
__device__ __forceinline__ void ldmx4t(uint32_t* r, uint32_t a) {
    asm volatile("ldmatrix.sync.aligned.m8n8.x4.trans.shared.b16 {%0,%1,%2,%3}, [%4];"
                 : "=r"(r[0]), "=r"(r[1]), "=r"(r[2]), "=r"(r[3]) : "r"(a));
}
__device__ __forceinline__ void mma16816(float* c, const uint32_t* a, const uint32_t* b) {
    asm volatile("mma.sync.aligned.m16n8k16.row.col.f32.bf16.bf16.f32 "
                 "{%0,%1,%2,%3}, {%4,%5,%6,%7}, {%8,%9}, {%0,%1,%2,%3};"
                 : "+f"(c[0]), "+f"(c[1]), "+f"(c[2]), "+f"(c[3])
                 : "r"(a[0]), "r"(a[1]), "r"(a[2]), "r"(a[3]), "r"(b[0]), "r"(b[1]));
}
__device__ __forceinline__ __nv_bfloat162 pack2(float a, float b) {
    __nv_bfloat162 v;
    v.x = __float2bfloat16(a);
    v.y = __float2bfloat16(b);
    return v;
}

// ------------------------------- init kernels -------------------------------
__global__ void k_init(const float* __restrict__ Z, float* __restrict__ Z0) {
    size_t i = (size_t)blockIdx.x * blockDim.x + threadIdx.x;
    size_t total = (size_t)BATCH * NP1 * ZLD;
    if (i >= total) return;
    size_t row = i / ZLD;
    int c = (int)(i % ZLD);
    if (c < DP1) {
        size_t fi = row * DP1 + c;
        float z = Z[fi];
        Z0[fi]    = z;
        g_acc[fi] = 0.0f;
        g_Zh[i]   = __float2bfloat16(z);
    } else {
        g_Zh[i] = __float2bfloat16(0.0f);
    }
}

__global__ void k_convPQ(const float* __restrict__ allparam) {
    int i = blockIdx.x * blockDim.x + threadIdx.x;
    if (i < NLAYER * 2 * 128 * 128) g_PQ[i] = __float2bfloat16(allparam[i]);
}

// -------------------------------- k_gram ------------------------------------
// G = Z[:256]^T @ Z[:256]  per batch, 144x144 out (pads auto-zero), K = 256.
__global__ __launch_bounds__(288, 2) void k_gram() {
    int b = blockIdx.x;
    const bf16* Zb = g_Zh + (size_t)b * NP1 * ZLD;
    bf16*       Gb = g_G  + (size_t)b * PD * PD;

    __shared__ bf16 Zs[32][152];

    int tid = threadIdx.x, lane = tid & 31, warp = tid >> 5;
    int wm = (warp / 3) * 48, wn = (warp % 3) * 48;
    int mat = lane >> 3, l7 = lane & 7;

    float acc[3][3][2][4];
#pragma unroll
    for (int a = 0; a < 3; a++)
#pragma unroll
        for (int c = 0; c < 3; c++)
#pragma unroll
            for (int h = 0; h < 2; h++)
#pragma unroll
                for (int e = 0; e < 4; e++) acc[a][c][h][e] = 0.0f;

    for (int k0 = 0; k0 < 256; k0 += 32) {
        for (int i = tid; i < 32 * 18; i += 288) {
            int r = i / 18, c = i % 18;
            *(uint4*)&Zs[r][c * 8] =
                *(const uint4*)&Zb[(size_t)(k0 + r) * ZLD + c * 8];
        }
        __syncthreads();
#pragma unroll
        for (int kk = 0; kk < 32; kk += 16) {
            uint32_t afr[3][4];
            int arow = kk + ((mat >> 1) << 3) + l7;
#pragma unroll
            for (int mi = 0; mi < 3; mi++) {
                int acol = wm + mi * 16 + ((mat & 1) << 3);
                ldmx4t(afr[mi], smaddr(&Zs[arow][acol]));
            }
            int brow = kk + ((mat & 1) << 3) + l7;
#pragma unroll
            for (int ni = 0; ni < 3; ni++) {
                uint32_t bfr[4];
                int bcol = wn + ni * 16 + ((mat >> 1) << 3);
                ldmx4t(bfr, smaddr(&Zs[brow][bcol]));
#pragma unroll
                for (int mi = 0; mi < 3; mi++) {
                    mma16816(acc[mi][ni][0], afr[mi], bfr + 0);
                    mma16816(acc[mi][ni][1], afr[mi], bfr + 2);
                }
            }
        }
        __syncthreads();
    }

    int g = lane >> 2, t4 = lane & 3;
#pragma unroll
    for (int mi = 0; mi < 3; mi++)
#pragma unroll
        for (int ni = 0; ni < 3; ni++)
#pragma unroll
            for (int h = 0; h < 2; h++) {
                float* c = acc[mi][ni][h];
                int row = wm + mi * 16 + g;
                int col = wn + ni * 16 + h * 8 + 2 * t4;
                *(__nv_bfloat162*)&Gb[row * PD + col]       = pack2(c[0], c[1]);
                *(__nv_bfloat162*)&Gb[(row + 8) * PD + col] = pack2(c[2], c[3]);
            }
}

// -------------------------------- k_pqw -------------------------------------
// stage1: S = G @ P^T  (K=128; S[:,128] = G[:,128]) kept in smem
// stage2: W = Q @ S    (K=128; pad rows of Q are zero -> W pads zero)
extern __shared__ char sm_pqw[];
__global__ __launch_bounds__(288, 2) void k_pqw(int layer) {
    int b = blockIdx.x;
    const bf16* Gb = g_G + (size_t)b * PD * PD;
    bf16*       Wb = g_W + (size_t)b * PD * PD;
    const bf16* P  = g_PQ + ((size_t)layer * 2 + 0) * 128 * 128;
    const bf16* Q  = g_PQ + ((size_t)layer * 2 + 1) * 128 * 128;

    bf16 (*As)[40]  = (bf16(*)[40])sm_pqw;                       // 144 x 40
    bf16 (*Bs)[40]  = (bf16(*)[40])(sm_pqw + 144 * 40 * 2);      // 144 x 40
    bf16 (*Ss)[152] = (bf16(*)[152])(sm_pqw + 2 * 144 * 40 * 2); // 128 x 152

    int tid = threadIdx.x, lane = tid & 31, warp = tid >> 5;
    int wm = (warp / 3) * 48, wn = (warp % 3) * 48;
    int mat = lane >> 3, l7 = lane & 7;
    int g = lane >> 2, t4 = lane & 3;

    float acc[3][3][2][4];
#pragma unroll
    for (int a = 0; a < 3; a++)
#pragma unroll
        for (int c = 0; c < 3; c++)
#pragma unroll
            for (int h = 0; h < 2; h++)
#pragma unroll
                for (int e = 0; e < 4; e++) acc[a][c][h][e] = 0.0f;

    const uint4 zero4 = make_uint4(0, 0, 0, 0);

    // ---- stage 1: S = G @ P^T ----
    for (int k0 = 0; k0 < 128; k0 += 32) {
        for (int i = tid; i < 144 * 4; i += 288) {
            int r = i / 4, c = i % 4;
            *(uint4*)&As[r][c * 8] = *(const uint4*)&Gb[r * PD + k0 + c * 8];
        }
        for (int i = tid; i < 144 * 4; i += 288) {
            int r = i / 4, c = i % 4;
            uint4 v = (r < 128) ? *(const uint4*)&P[r * 128 + k0 + c * 8] : zero4;
            *(uint4*)&Bs[r][c * 8] = v;
        }
        __syncthreads();
#pragma unroll
        for (int kk = 0; kk < 32; kk += 16) {
            uint32_t afr[3][4];
#pragma unroll
            for (int mi = 0; mi < 3; mi++) {
                int arow = wm + mi * 16 + ((mat & 1) << 3) + l7;
                int acol = kk + ((mat >> 1) << 3);
                ldmx4(afr[mi], smaddr(&As[arow][acol]));
            }
#pragma unroll
            for (int ni = 0; ni < 3; ni++) {
                uint32_t bfr[4];
                int brow = wn + ni * 16 + ((mat >> 1) << 3) + l7;
                int bcol = kk + ((mat & 1) << 3);
                ldmx4(bfr, smaddr(&Bs[brow][bcol]));
#pragma unroll
                for (int mi = 0; mi < 3; mi++) {
                    mma16816(acc[mi][ni][0], afr[mi], bfr + 0);
                    mma16816(acc[mi][ni][1], afr[mi], bfr + 2);
                }
            }
        }
        __syncthreads();
    }

    // write S (rows < 128 feed stage 2)
#pragma unroll
    for (int mi = 0; mi < 3; mi++)
#pragma unroll
        for (int ni = 0; ni < 3; ni++)
#pragma unroll
            for (int h = 0; h < 2; h++) {
                float* c = acc[mi][ni][h];
                int row = wm + mi * 16 + g;
                int col = wn + ni * 16 + h * 8 + 2 * t4;
                if (row < 128)
                    *(__nv_bfloat162*)&Ss[row][col] = pack2(c[0], c[1]);
                if (row + 8 < 128)
                    *(__nv_bfloat162*)&Ss[row + 8][col] = pack2(c[2], c[3]);
            }
    __syncthreads();
    // S[:,128] = G[:,128]
    for (int i = tid; i < 128; i += 288) Ss[i][128] = Gb[i * PD + 128];
    __syncthreads();

    // ---- stage 2: W = Q @ S ----
#pragma unroll
    for (int a = 0; a < 3; a++)
#pragma unroll
        for (int c = 0; c < 3; c++)
#pragma unroll
            for (int h = 0; h < 2; h++)
#pragma unroll
                for (int e = 0; e < 4; e++) acc[a][c][h][e] = 0.0f;

    for (int k0 = 0; k0 < 128; k0 += 32) {
        for (int i = tid; i < 144 * 4; i += 288) {
            int r = i / 4, c = i % 4;
            uint4 v = (r < 128) ? *(const uint4*)&Q[r * 128 + k0 + c * 8] : zero4;
            *(uint4*)&As[r][c * 8] = v;
        }
        __syncthreads();
#pragma unroll
        for (int kk = 0; kk < 32; kk += 16) {
            uint32_t afr[3][4];
#pragma unroll
            for (int mi = 0; mi < 3; mi++) {
                int arow = wm + mi * 16 + ((mat & 1) << 3) + l7;
                int acol = kk + ((mat >> 1) << 3);
                ldmx4(afr[mi], smaddr(&As[arow][acol]));
            }
#pragma unroll
            for (int ni = 0; ni < 3; ni++) {
                uint32_t bfr[4];
                int brow = k0 + kk + ((mat & 1) << 3) + l7;
                int bcol = wn + ni * 16 + ((mat >> 1) << 3);
                ldmx4t(bfr, smaddr(&Ss[brow][bcol]));
#pragma unroll
                for (int mi = 0; mi < 3; mi++) {
                    mma16816(acc[mi][ni][0], afr[mi], bfr + 0);
                    mma16816(acc[mi][ni][1], afr[mi], bfr + 2);
                }
            }
        }
        __syncthreads();
    }

#pragma unroll
    for (int mi = 0; mi < 3; mi++)
#pragma unroll
        for (int ni = 0; ni < 3; ni++)
#pragma unroll
            for (int h = 0; h < 2; h++) {
                float* c = acc[mi][ni][h];
                int row = wm + mi * 16 + g;
                int col = wn + ni * 16 + h * 8 + 2 * t4;
                *(__nv_bfloat162*)&Wb[row * PD + col]       = pack2(c[0], c[1]);
                *(__nv_bfloat162*)&Wb[(row + 8) * PD + col] = pack2(c[2], c[3]);
            }
}

// -------------------------------- k_out -------------------------------------
// R = Z @ W / 256 ; Zout = Zin + R + acc ; acc += R * gamma ; Zh = bf16(Zout)
__global__ __launch_bounds__(288, 2) void k_out(const float* __restrict__ Zin,
                                                const float* __restrict__ gamma_l,
                                                float* __restrict__ Zout) {
    int b = blockIdx.y;
    int n0base = blockIdx.x * PD;   // 0 or 144

    const bf16* Zb = g_Zh + (size_t)b * NP1 * ZLD;
    const bf16* Wb = g_W  + (size_t)b * PD * PD;

    __shared__ bf16 As[144][56];
    __shared__ bf16 Ws[48][152];

    int tid = threadIdx.x, lane = tid & 31, warp = tid >> 5;
    int wm = (warp / 3) * 48, wn = (warp % 3) * 48;
    int mat = lane >> 3, l7 = lane & 7;
    int g = lane >> 2, t4 = lane & 3;

    float acc[3][3][2][4];
#pragma unroll
    for (int a = 0; a < 3; a++)
#pragma unroll
        for (int c = 0; c < 3; c++)
#pragma unroll
            for (int h = 0; h < 2; h++)
#pragma unroll
                for (int e = 0; e < 4; e++) acc[a][c][h][e] = 0.0f;

    const uint4 zero4 = make_uint4(0, 0, 0, 0);

    for (int k0 = 0; k0 < PD; k0 += 48) {
        for (int i = tid; i < 144 * 6; i += 288) {
            int r = i / 6, c = i % 6;
            int gr = n0base + r;
            uint4 v = (gr < NP1)
                ? *(const uint4*)&Zb[(size_t)gr * ZLD + k0 + c * 8] : zero4;
            *(uint4*)&As[r][c * 8] = v;
        }
        for (int i = tid; i < 48 * 18; i += 288) {
            int r = i / 18, c = i % 18;
            *(uint4*)&Ws[r][c * 8] = *(const uint4*)&Wb[(k0 + r) * PD + c * 8];
        }
        __syncthreads();
#pragma unroll
        for (int kk = 0; kk < 48; kk += 16) {
            uint32_t afr[3][4];
#pragma unroll
            for (int mi = 0; mi < 3; mi++) {
                int arow = wm + mi * 16 + ((mat & 1) << 3) + l7;
                int acol = kk + ((mat >> 1) << 3);
                ldmx4(afr[mi], smaddr(&As[arow][acol]));
            }
            int brow = kk + ((mat & 1) << 3) + l7;
#pragma unroll
            for (int ni = 0; ni < 3; ni++) {
                uint32_t bfr[4];
                int bcol = wn + ni * 16 + ((mat >> 1) << 3);
                ldmx4t(bfr, smaddr(&Ws[brow][bcol]));
#pragma unroll
                for (int mi = 0; mi < 3; mi++) {
                    mma16816(acc[mi][ni][0], afr[mi], bfr + 0);
                    mma16816(acc[mi][ni][1], afr[mi], bfr + 2);
                }
            }
        }
        __syncthreads();
    }

    const float inv = 1.0f / 256.0f;
#pragma unroll
    for (int mi = 0; mi < 3; mi++)
#pragma unroll
        for (int ni = 0; ni < 3; ni++)
#pragma unroll
            for (int h = 0; h < 2; h++) {
                float* c = acc[mi][ni][h];
                int row0 = wm + mi * 16 + g;
                int col0 = wn + ni * 16 + h * 8 + 2 * t4;
#pragma unroll
                for (int e = 0; e < 4; e++) {
                    int n = n0base + row0 + ((e >> 1) ? 8 : 0);
                    int j = col0 + (e & 1);
                    if (n >= NP1 || j >= DP1) continue;
                    size_t fidx = ((size_t)b * NP1 + n) * DP1 + j;
                    float r = c[e] * inv;
                    float a = g_acc[fidx];
                    float zo = Zin[fidx] + r + a;
                    Zout[fidx]  = zo;
                    g_acc[fidx] = a + r * gamma_l[n * DP1 + j];
                    g_Zh[(size_t)b * NP1 * ZLD + (size_t)n * ZLD + j] =
                        __float2bfloat16(zo);
                }
            }
}

// ------------------------------ kernel_launch -------------------------------
extern "C" void kernel_launch(void* const* d_in, const int* in_sizes, int n_in,
                              void* d_out, int out_size) {
    const float* Z        = (const float*)d_in[0];
    const float* allparam = (const float*)d_in[1];
    const float* gamma    = (const float*)d_in[2];

    float* Z0 = (float*)d_out;
    float* Z1 = nullptr;
    cudaGetSymbolAddress((void**)&Z1, g_Zalt);

    const int pqw_smem = (2 * 144 * 40 + 128 * 152) * (int)sizeof(bf16);
    cudaFuncSetAttribute(k_pqw, cudaFuncAttributeMaxDynamicSharedMemorySize,
                         pqw_smem);

    size_t total = (size_t)BATCH * NP1 * ZLD;
    k_init<<<(int)((total + 255) / 256), 256>>>(Z, Z0);
    k_convPQ<<<(NLAYER * 2 * 128 * 128 + 255) / 256, 256>>>(allparam);

    const float* zin = Z0;
    float* zout = Z1;
    for (int l = 0; l < NLAYER; l++) {
        k_gram<<<BATCH, 288>>>();
        k_pqw<<<BATCH, 288, pqw_smem>>>(l);
        k_out<<<dim3(2, BATCH), 288>>>(zin, gamma + (size_t)l * NP1 * DP1, zout);
        float* t = (float*)zin; zin = zout; zout = t;
    }
    // after 4 swaps the final Z is in d_out
}

// round 4
// speedup vs baseline: 5.9663x; 1.6637x over previous
#include <cuda_runtime.h>
#include <cuda_bf16.h>
#include <cstdint>

#define BATCH  512
#define NP1    257
#define DP1    129
#define NLAYER 4
#define ZST    152     // Zh smem row stride (halves): 304B, conflict-free, >=144 data cols
#define GST    152     // G/S/W smem row stride: 304B, conflict-free, >=144 data cols
#define AST    129     // acc smem row stride (scalar access only)

typedef __nv_bfloat16 bf16;

__device__ bf16 g_PQ[NLAYER * 2 * 128 * 128];   // bf16 P,Q weights

// ------------------------------ mma helpers --------------------------------
__device__ __forceinline__ uint32_t smaddr(const void* p) {
    return (uint32_t)__cvta_generic_to_shared(p);
}
__device__ __forceinline__ void ldmx4(uint32_t* r, uint32_t a) {
    asm volatile("ldmatrix.sync.aligned.m8n8.x4.shared.b16 {%0,%1,%2,%3}, [%4];"
                 : "=r"(r[0]), "=r"(r[1]), "=r"(r[2]), "=r"(r[3]) : "r"(a));
}
__device__ __forceinline__ void ldmx4t(uint32_t* r, uint32_t a) {
    asm volatile("ldmatrix.sync.aligned.m8n8.x4.trans.shared.b16 {%0,%1,%2,%3}, [%4];"
                 : "=r"(r[0]), "=r"(r[1]), "=r"(r[2]), "=r"(r[3]) : "r"(a));
}
__device__ __forceinline__ void mma16816(float* c, const uint32_t* a, const uint32_t* b) {
    asm volatile("mma.sync.aligned.m16n8k16.row.col.f32.bf16.bf16.f32 "
                 "{%0,%1,%2,%3}, {%4,%5,%6,%7}, {%8,%9}, {%0,%1,%2,%3};"
                 : "+f"(c[0]), "+f"(c[1]), "+f"(c[2]), "+f"(c[3])
                 : "r"(a[0]), "r"(a[1]), "r"(a[2]), "r"(a[3]), "r"(b[0]), "r"(b[1]));
}
__device__ __forceinline__ __nv_bfloat162 pack2(float a, float b) {
    __nv_bfloat162 v;
    v.x = __float2bfloat16(a);
    v.y = __float2bfloat16(b);
    return v;
}

// ------------------------------- convPQ -------------------------------------
__global__ void k_convPQ(const float* __restrict__ allparam) {
    int i = blockIdx.x * blockDim.x + threadIdx.x;
    if (i < NLAYER * 2 * 128 * 128) g_PQ[i] = __float2bfloat16(allparam[i]);
}

// ------------------------------- k_fused ------------------------------------
// One CTA per batch. All 4 layers; Zh/G/S/acc SMEM-resident; Z fp32 streams
// through global (in place in d_out).
extern __shared__ bf16 sm_f[];

__global__ __launch_bounds__(288, 1) void k_fused(const float* __restrict__ Zin0,
                                                  const float* __restrict__ gamma,
                                                  float* __restrict__ Zio) {
    bf16* Zh = sm_f;                       // 257 x 152
    bf16* Gs = Zh + 257 * ZST;             // 144 x 152  (Gram, later W)
    bf16* Ss = Gs + 144 * GST;             // 144 x 152  (S = G P^T)
    bf16* Ac = Ss + 144 * GST;             // 257 x 129  (bf16 running acc)

    int b = blockIdx.x;
    const float* Zb0 = Zin0 + (size_t)b * NP1 * DP1;
    float*       Zo  = Zio  + (size_t)b * NP1 * DP1;

    int tid = threadIdx.x, lane = tid & 31, warp = tid >> 5;
    int wm = (warp / 3) * 48, wn = (warp % 3) * 48;
    int mat = lane >> 3, l7 = lane & 7;
    int g = lane >> 2, t4 = lane & 3;

    // ---------------- init: Zh from input Z; acc = 0 ----------------
    for (int i = tid; i < 257 * 38; i += 288) {
        int r = i / 38, c4 = (i % 38) * 4;
#pragma unroll
        for (int u = 0; u < 4; u++) {
            int j = c4 + u;
            float v = (j < DP1) ? Zb0[(size_t)r * DP1 + j] : 0.0f;
            Zh[r * ZST + j] = __float2bfloat16(v);
        }
    }
    for (int i = tid; i < 257 * AST; i += 288)
        Ac[i] = __float2bfloat16(0.0f);
    __syncthreads();

    float acc[3][3][2][4];

    for (int l = 0; l < NLAYER; l++) {
        const bf16* P = g_PQ + ((size_t)l * 2 + 0) * 128 * 128;
        const bf16* Q = g_PQ + ((size_t)l * 2 + 1) * 128 * 128;
        const float* gml = gamma + (size_t)l * NP1 * DP1;
        const float* Zi  = (l == 0) ? Zb0 : Zo;

        // ================= Phase 1: G = Zh[:256]^T Zh[:256] =================
#pragma unroll
        for (int a = 0; a < 3; a++)
#pragma unroll
            for (int c = 0; c < 3; c++)
#pragma unroll
                for (int h = 0; h < 2; h++)
#pragma unroll
                    for (int e = 0; e < 4; e++) acc[a][c][h][e] = 0.0f;

        for (int kk = 0; kk < 256; kk += 16) {
            uint32_t afr[3][4];
            int arow = kk + ((mat >> 1) << 3) + l7;
#pragma unroll
            for (int mi = 0; mi < 3; mi++) {
                int acol = wm + mi * 16 + ((mat & 1) << 3);
                ldmx4t(afr[mi], smaddr(&Zh[arow * ZST + acol]));
            }
            int brow = kk + ((mat & 1) << 3) + l7;
#pragma unroll
            for (int ni = 0; ni < 3; ni++) {
                uint32_t bfr[4];
                int bcol = wn + ni * 16 + ((mat >> 1) << 3);
                ldmx4t(bfr, smaddr(&Zh[brow * ZST + bcol]));
#pragma unroll
                for (int mi = 0; mi < 3; mi++) {
                    mma16816(acc[mi][ni][0], afr[mi], bfr + 0);
                    mma16816(acc[mi][ni][1], afr[mi], bfr + 2);
                }
            }
        }
#pragma unroll
        for (int mi = 0; mi < 3; mi++)
#pragma unroll
            for (int ni = 0; ni < 3; ni++)
#pragma unroll
                for (int h = 0; h < 2; h++) {
                    float* c = acc[mi][ni][h];
                    int row = wm + mi * 16 + g;
                    int col = wn + ni * 16 + h * 8 + 2 * t4;
                    *(__nv_bfloat162*)&Gs[row * GST + col]       = pack2(c[0], c[1]);
                    *(__nv_bfloat162*)&Gs[(row + 8) * GST + col] = pack2(c[2], c[3]);
                }
        __syncthreads();

        // ================= Phase 2a: S = G @ P^T  (K=128) =================
#pragma unroll
        for (int a = 0; a < 3; a++)
#pragma unroll
            for (int c = 0; c < 3; c++)
#pragma unroll
                for (int h = 0; h < 2; h++)
#pragma unroll
                    for (int e = 0; e < 4; e++) acc[a][c][h][e] = 0.0f;

        for (int kk = 0; kk < 128; kk += 16) {
            uint32_t afr[3][4];
#pragma unroll
            for (int mi = 0; mi < 3; mi++) {
                int arow = wm + mi * 16 + ((mat & 1) << 3) + l7;
                int acol = kk + ((mat >> 1) << 3);
                ldmx4(afr[mi], smaddr(&Gs[arow * GST + acol]));
            }
#pragma unroll
            for (int ni = 0; ni < 3; ni++) {
                uint32_t bfr[4];
#pragma unroll
                for (int h = 0; h < 2; h++) {
                    int j = wn + ni * 16 + h * 8 + g;      // P row (n dim)
                    if (j < 128) {
                        bfr[2 * h + 0] = *(const uint32_t*)&P[j * 128 + kk + 2 * t4];
                        bfr[2 * h + 1] = *(const uint32_t*)&P[j * 128 + kk + 8 + 2 * t4];
                    } else {
                        bfr[2 * h + 0] = 0u;
                        bfr[2 * h + 1] = 0u;
                    }
                }
#pragma unroll
                for (int mi = 0; mi < 3; mi++) {
                    mma16816(acc[mi][ni][0], afr[mi], bfr + 0);
                    mma16816(acc[mi][ni][1], afr[mi], bfr + 2);
                }
            }
        }
#pragma unroll
        for (int mi = 0; mi < 3; mi++)
#pragma unroll
            for (int ni = 0; ni < 3; ni++)
#pragma unroll
                for (int h = 0; h < 2; h++) {
                    float* c = acc[mi][ni][h];
                    int row = wm + mi * 16 + g;
                    int col = wn + ni * 16 + h * 8 + 2 * t4;
                    *(__nv_bfloat162*)&Ss[row * GST + col]       = pack2(c[0], c[1]);
                    *(__nv_bfloat162*)&Ss[(row + 8) * GST + col] = pack2(c[2], c[3]);
                }
        __syncthreads();
        // patch S[:,128] = G[:,128]  (true column through P_full's unit corner)
        for (int i = tid; i < 144; i += 288) Ss[i * GST + 128] = Gs[i * GST + 128];
        __syncthreads();

        // ================= Phase 2b: W = Q @ S  (K=128, into Gs) ============
#pragma unroll
        for (int a = 0; a < 3; a++)
#pragma unroll
            for (int c = 0; c < 3; c++)
#pragma unroll
                for (int h = 0; h < 2; h++)
#pragma unroll
                    for (int e = 0; e < 4; e++) acc[a][c][h][e] = 0.0f;

        for (int kk = 0; kk < 128; kk += 16) {
            uint32_t afr[3][4];
#pragma unroll
            for (int mi = 0; mi < 3; mi++) {
                int m = wm + mi * 16 + g;
                afr[mi][0] = (m     < 128) ? *(const uint32_t*)&Q[m * 128 + kk + 2 * t4]           : 0u;
                afr[mi][1] = (m + 8 < 128) ? *(const uint32_t*)&Q[(m + 8) * 128 + kk + 2 * t4]     : 0u;
                afr[mi][2] = (m     < 128) ? *(const uint32_t*)&Q[m * 128 + kk + 8 + 2 * t4]       : 0u;
                afr[mi][3] = (m + 8 < 128) ? *(const uint32_t*)&Q[(m + 8) * 128 + kk + 8 + 2 * t4] : 0u;
            }
#pragma unroll
            for (int ni = 0; ni < 3; ni++) {
                uint32_t bfr[4];
                int brow = kk + ((mat & 1) << 3) + l7;
                int bcol = wn + ni * 16 + ((mat >> 1) << 3);
                ldmx4t(bfr, smaddr(&Ss[brow * GST + bcol]));
#pragma unroll
                for (int mi = 0; mi < 3; mi++) {
                    mma16816(acc[mi][ni][0], afr[mi], bfr + 0);
                    mma16816(acc[mi][ni][1], afr[mi], bfr + 2);
                }
            }
        }
#pragma unroll
        for (int mi = 0; mi < 3; mi++)
#pragma unroll
            for (int ni = 0; ni < 3; ni++)
#pragma unroll
                for (int h = 0; h < 2; h++) {
                    float* c = acc[mi][ni][h];
                    int row = wm + mi * 16 + g;
                    int col = wn + ni * 16 + h * 8 + 2 * t4;
                    *(__nv_bfloat162*)&Gs[row * GST + col]       = pack2(c[0], c[1]);
                    *(__nv_bfloat162*)&Gs[(row + 8) * GST + col] = pack2(c[2], c[3]);
                }
        __syncthreads();

        // ================= Phase 3: R = Zh @ W / 256; update ================
        // chunk 0: rows 0..143 ; chunk 1: rows 113..256 (outputs <144 dropped)
#pragma unroll
        for (int c0 = 0; c0 < 2; c0++) {
            int base = c0 ? 113 : 0;
#pragma unroll
            for (int a = 0; a < 3; a++)
#pragma unroll
                for (int c = 0; c < 3; c++)
#pragma unroll
                    for (int h = 0; h < 2; h++)
#pragma unroll
                        for (int e = 0; e < 4; e++) acc[a][c][h][e] = 0.0f;

            for (int kk = 0; kk < 144; kk += 16) {
                uint32_t afr[3][4];
#pragma unroll
                for (int mi = 0; mi < 3; mi++) {
                    int arow = base + wm + mi * 16 + ((mat & 1) << 3) + l7;
                    int acol = kk + ((mat >> 1) << 3);
                    ldmx4(afr[mi], smaddr(&Zh[arow * ZST + acol]));
                }
#pragma unroll
                for (int ni = 0; ni < 3; ni++) {
                    uint32_t bfr[4];
                    int brow = kk + ((mat & 1) << 3) + l7;
                    int bcol = wn + ni * 16 + ((mat >> 1) << 3);
                    ldmx4t(bfr, smaddr(&Gs[brow * GST + bcol]));
#pragma unroll
                    for (int mi = 0; mi < 3; mi++) {
                        mma16816(acc[mi][ni][0], afr[mi], bfr + 0);
                        mma16816(acc[mi][ni][1], afr[mi], bfr + 2);
                    }
                }
            }
            __syncthreads();   // all chunk GEMM reads of Zh done before writes

            const float inv = 1.0f / 256.0f;
#pragma unroll
            for (int mi = 0; mi < 3; mi++)
#pragma unroll
                for (int ni = 0; ni < 3; ni++)
#pragma unroll
                    for (int h = 0; h < 2; h++) {
                        float* cc = acc[mi][ni][h];
                        int row0 = wm + mi * 16 + g;
                        int col0 = wn + ni * 16 + h * 8 + 2 * t4;
#pragma unroll
                        for (int e = 0; e < 4; e++) {
                            int n = base + row0 + ((e >> 1) ? 8 : 0);
                            int j = col0 + (e & 1);
                            if (n < NP1 && j < DP1 && (c0 == 0 || n >= 144)) {
                                size_t fi = (size_t)n * DP1 + j;
                                float r = cc[e] * inv;
                                float a = __bfloat162float(Ac[n * AST + j]);
                                float zo = Zi[fi] + r + a;
                                Zo[fi] = zo;
                                Ac[n * AST + j] =
                                    __float2bfloat16(a + r * gml[fi]);
                                Zh[n * ZST + j] = __float2bfloat16(zo);
                            }
                        }
                    }
            __syncthreads();
        }
    }
}

// ------------------------------ kernel_launch -------------------------------
extern "C" void kernel_launch(void* const* d_in, const int* in_sizes, int n_in,
                              void* d_out, int out_size) {
    const float* Z        = (const float*)d_in[0];
    const float* allparam = (const float*)d_in[1];
    const float* gamma    = (const float*)d_in[2];

    const int smem_bytes = (257 * ZST + 2 * 144 * GST + 257 * AST) * (int)sizeof(bf16);
    cudaFuncSetAttribute(k_fused, cudaFuncAttributeMaxDynamicSharedMemorySize,
                         smem_bytes);

    k_convPQ<<<(NLAYER * 2 * 128 * 128 + 255) / 256, 256>>>(allparam);
    k_fused<<<BATCH, 288, smem_bytes>>>(Z, gamma, (float*)d_out);
}

// round 5
// speedup vs baseline: 6.0624x; 1.0161x over previous
#include <cuda_runtime.h>
#include <cuda_bf16.h>
#include <cstdint>

#define BATCH  512
#define NP1    257
#define DP1    129
#define NLAYER 4
#define ZST    152     // Zh smem row stride (halves)
#define GST    152     // G/S/W smem row stride
#define AST    129     // acc smem row stride (scalar access only)

typedef __nv_bfloat16 bf16;

__device__ bf16 g_PQ[NLAYER * 2 * 128 * 128];   // bf16 P,Q weights

// ------------------------------ mma helpers --------------------------------
__device__ __forceinline__ uint32_t smaddr(const void* p) {
    return (uint32_t)__cvta_generic_to_shared(p);
}
__device__ __forceinline__ void ldmx4(uint32_t* r, uint32_t a) {
    asm volatile("ldmatrix.sync.aligned.m8n8.x4.shared.b16 {%0,%1,%2,%3}, [%4];"
                 : "=r"(r[0]), "=r"(r[1]), "=r"(r[2]), "=r"(r[3]) : "r"(a));
}
__device__ __forceinline__ void ldmx4t(uint32_t* r, uint32_t a) {
    asm volatile("ldmatrix.sync.aligned.m8n8.x4.trans.shared.b16 {%0,%1,%2,%3}, [%4];"
                 : "=r"(r[0]), "=r"(r[1]), "=r"(r[2]), "=r"(r[3]) : "r"(a));
}
__device__ __forceinline__ void mma16816(float* c, const uint32_t* a, const uint32_t* b) {
    asm volatile("mma.sync.aligned.m16n8k16.row.col.f32.bf16.bf16.f32 "
                 "{%0,%1,%2,%3}, {%4,%5,%6,%7}, {%8,%9}, {%0,%1,%2,%3};"
                 : "+f"(c[0]), "+f"(c[1]), "+f"(c[2]), "+f"(c[3])
                 : "r"(a[0]), "r"(a[1]), "r"(a[2]), "r"(a[3]), "r"(b[0]), "r"(b[1]));
}
__device__ __forceinline__ __nv_bfloat162 pack2(float a, float b) {
    __nv_bfloat162 v;
    v.x = __float2bfloat16(a);
    v.y = __float2bfloat16(b);
    return v;
}

// ------------------------------- convPQ -------------------------------------
__global__ void k_convPQ(const float* __restrict__ allparam) {
    int i = blockIdx.x * blockDim.x + threadIdx.x;
    if (i < NLAYER * 2 * 128 * 128) g_PQ[i] = __float2bfloat16(allparam[i]);
}

// ------------------------------- k_fused ------------------------------------
extern __shared__ bf16 sm_f[];

__global__ __launch_bounds__(288, 1) void k_fused(const float* __restrict__ Zin0,
                                                  const float* __restrict__ gamma,
                                                  float* __restrict__ Zio) {
    bf16* Zh = sm_f;                       // 257 x 152
    bf16* Gs = Zh + 257 * ZST;             // 144 x 152  (Gram, later W)
    bf16* Ss = Gs + 144 * GST;             // 144 x 152  (S = G P^T)
    bf16* Ac = Ss + 144 * GST;             // 257 x 129  (bf16 running acc)

    int b = blockIdx.x;
    const float* Zb0 = Zin0 + (size_t)b * NP1 * DP1;
    float*       Zo  = Zio  + (size_t)b * NP1 * DP1;

    int tid = threadIdx.x, lane = tid & 31, warp = tid >> 5;
    int wm = (warp / 3) * 48, wn = (warp % 3) * 48;
    int mat = lane >> 3, l7 = lane & 7;
    int g = lane >> 2, t4 = lane & 3;

    // ---------------- init: Zh from input Z; acc = 0 ----------------
    for (int i = tid; i < 257 * 38; i += 288) {
        int r = i / 38, c4 = (i % 38) * 4;
#pragma unroll
        for (int u = 0; u < 4; u++) {
            int j = c4 + u;
            float v = (j < DP1) ? Zb0[(size_t)r * DP1 + j] : 0.0f;
            Zh[r * ZST + j] = __float2bfloat16(v);
        }
    }
    for (int i = tid; i < 257 * AST; i += 288)
        Ac[i] = __float2bfloat16(0.0f);
    __syncthreads();

    float acc[3][3][2][4];
    uint32_t afr[2][3][4], bfr[2][3][4];

    for (int l = 0; l < NLAYER; l++) {
        const bf16* P = g_PQ + ((size_t)l * 2 + 0) * 128 * 128;
        const bf16* Q = g_PQ + ((size_t)l * 2 + 1) * 128 * 128;
        const float* gml = gamma + (size_t)l * NP1 * DP1;
        const float* Zi  = (l == 0) ? Zb0 : Zo;

        // -- fragment loaders (double-buffered call sites) --
        auto p1_loadA = [&](int kk, uint32_t fr[3][4]) {
            int arow = kk + ((mat >> 1) << 3) + l7;
#pragma unroll
            for (int mi = 0; mi < 3; mi++)
                ldmx4t(fr[mi], smaddr(&Zh[arow * ZST + wm + mi * 16 + ((mat & 1) << 3)]));
        };
        auto p1_loadB = [&](int kk, uint32_t fr[3][4]) {
            int brow = kk + ((mat & 1) << 3) + l7;
#pragma unroll
            for (int ni = 0; ni < 3; ni++)
                ldmx4t(fr[ni], smaddr(&Zh[brow * ZST + wn + ni * 16 + ((mat >> 1) << 3)]));
        };
        auto p2a_loadA = [&](int kk, uint32_t fr[3][4]) {
#pragma unroll
            for (int mi = 0; mi < 3; mi++) {
                int arow = wm + mi * 16 + ((mat & 1) << 3) + l7;
                ldmx4(fr[mi], smaddr(&Gs[arow * GST + kk + ((mat >> 1) << 3)]));
            }
        };
        auto p2a_loadB = [&](int kk, uint32_t fr[3][4]) {
#pragma unroll
            for (int ni = 0; ni < 3; ni++)
#pragma unroll
                for (int h = 0; h < 2; h++) {
                    int j = wn + ni * 16 + h * 8 + g;
                    if (j < 128) {
                        fr[ni][2 * h + 0] = *(const uint32_t*)&P[j * 128 + kk + 2 * t4];
                        fr[ni][2 * h + 1] = *(const uint32_t*)&P[j * 128 + kk + 8 + 2 * t4];
                    } else {
                        fr[ni][2 * h + 0] = 0u;
                        fr[ni][2 * h + 1] = 0u;
                    }
                }
        };
        auto p2b_loadA = [&](int kk, uint32_t fr[3][4]) {
#pragma unroll
            for (int mi = 0; mi < 3; mi++) {
                int m = wm + mi * 16 + g;
                fr[mi][0] = (m     < 128) ? *(const uint32_t*)&Q[m * 128 + kk + 2 * t4]           : 0u;
                fr[mi][1] = (m + 8 < 128) ? *(const uint32_t*)&Q[(m + 8) * 128 + kk + 2 * t4]     : 0u;
                fr[mi][2] = (m     < 128) ? *(const uint32_t*)&Q[m * 128 + kk + 8 + 2 * t4]       : 0u;
                fr[mi][3] = (m + 8 < 128) ? *(const uint32_t*)&Q[(m + 8) * 128 + kk + 8 + 2 * t4] : 0u;
            }
        };
        auto p2b_loadB = [&](int kk, uint32_t fr[3][4]) {
            int brow = kk + ((mat & 1) << 3) + l7;
#pragma unroll
            for (int ni = 0; ni < 3; ni++)
                ldmx4t(fr[ni], smaddr(&Ss[brow * GST + wn + ni * 16 + ((mat >> 1) << 3)]));
        };
        auto p3_loadA = [&](int base, int kk, uint32_t fr[3][4]) {
#pragma unroll
            for (int mi = 0; mi < 3; mi++) {
                int arow = base + wm + mi * 16 + ((mat & 1) << 3) + l7;
                ldmx4(fr[mi], smaddr(&Zh[arow * ZST + kk + ((mat >> 1) << 3)]));
            }
        };
        auto p3_loadB = [&](int kk, uint32_t fr[3][4]) {
            int brow = kk + ((mat & 1) << 3) + l7;
#pragma unroll
            for (int ni = 0; ni < 3; ni++)
                ldmx4t(fr[ni], smaddr(&Gs[brow * GST + wn + ni * 16 + ((mat >> 1) << 3)]));
        };
        auto zero_acc = [&]() {
#pragma unroll
            for (int a = 0; a < 3; a++)
#pragma unroll
                for (int c = 0; c < 3; c++)
#pragma unroll
                    for (int h = 0; h < 2; h++)
#pragma unroll
                        for (int e = 0; e < 4; e++) acc[a][c][h][e] = 0.0f;
        };
        auto do_mmas = [&](int cur) {
#pragma unroll
            for (int ni = 0; ni < 3; ni++)
#pragma unroll
                for (int mi = 0; mi < 3; mi++) {
                    mma16816(acc[mi][ni][0], afr[cur][mi], bfr[cur][ni] + 0);
                    mma16816(acc[mi][ni][1], afr[cur][mi], bfr[cur][ni] + 2);
                }
        };

        // ================= Phase 1: G = Zh[:256]^T Zh[:256] =================
        zero_acc();
        p1_loadA(0, afr[0]);
        p1_loadB(0, bfr[0]);
#pragma unroll 2
        for (int kk = 0; kk < 256; kk += 16) {
            int cur = (kk >> 4) & 1, nx = cur ^ 1;
            if (kk + 16 < 256) { p1_loadA(kk + 16, afr[nx]); p1_loadB(kk + 16, bfr[nx]); }
            do_mmas(cur);
        }
#pragma unroll
        for (int mi = 0; mi < 3; mi++)
#pragma unroll
            for (int ni = 0; ni < 3; ni++)
#pragma unroll
                for (int h = 0; h < 2; h++) {
                    float* c = acc[mi][ni][h];
                    int row = wm + mi * 16 + g;
                    int col = wn + ni * 16 + h * 8 + 2 * t4;
                    *(__nv_bfloat162*)&Gs[row * GST + col]       = pack2(c[0], c[1]);
                    *(__nv_bfloat162*)&Gs[(row + 8) * GST + col] = pack2(c[2], c[3]);
                }
        __syncthreads();

        // ================= Phase 2a: S = G @ P^T  (K=128) =================
        zero_acc();
        p2a_loadA(0, afr[0]);
        p2a_loadB(0, bfr[0]);
#pragma unroll 2
        for (int kk = 0; kk < 128; kk += 16) {
            int cur = (kk >> 4) & 1, nx = cur ^ 1;
            if (kk + 16 < 128) { p2a_loadA(kk + 16, afr[nx]); p2a_loadB(kk + 16, bfr[nx]); }
            do_mmas(cur);
        }
        // store S; fold in S[:,128] = G[:,128] (P_full's unit corner column)
#pragma unroll
        for (int mi = 0; mi < 3; mi++)
#pragma unroll
            for (int ni = 0; ni < 3; ni++)
#pragma unroll
                for (int h = 0; h < 2; h++) {
                    float* c = acc[mi][ni][h];
                    int row = wm + mi * 16 + g;
                    int col = wn + ni * 16 + h * 8 + 2 * t4;
                    __nv_bfloat162 v0 = pack2(c[0], c[1]);
                    __nv_bfloat162 v1 = pack2(c[2], c[3]);
                    if (col == 128) {
                        v0.x = Gs[row * GST + 128];
                        v1.x = Gs[(row + 8) * GST + 128];
                    }
                    *(__nv_bfloat162*)&Ss[row * GST + col]       = v0;
                    *(__nv_bfloat162*)&Ss[(row + 8) * GST + col] = v1;
                }
        __syncthreads();

        // ================= Phase 2b: W = Q @ S  (K=128, into Gs) ============
        zero_acc();
        p2b_loadA(0, afr[0]);
        p2b_loadB(0, bfr[0]);
#pragma unroll 2
        for (int kk = 0; kk < 128; kk += 16) {
            int cur = (kk >> 4) & 1, nx = cur ^ 1;
            if (kk + 16 < 128) { p2b_loadA(kk + 16, afr[nx]); p2b_loadB(kk + 16, bfr[nx]); }
            do_mmas(cur);
        }
#pragma unroll
        for (int mi = 0; mi < 3; mi++)
#pragma unroll
            for (int ni = 0; ni < 3; ni++)
#pragma unroll
                for (int h = 0; h < 2; h++) {
                    float* c = acc[mi][ni][h];
                    int row = wm + mi * 16 + g;
                    int col = wn + ni * 16 + h * 8 + 2 * t4;
                    *(__nv_bfloat162*)&Gs[row * GST + col]       = pack2(c[0], c[1]);
                    *(__nv_bfloat162*)&Gs[(row + 8) * GST + col] = pack2(c[2], c[3]);
                }
        __syncthreads();

        // ================= Phase 3: R = Zh @ W / 256; update ================
        // chunk 0: rows 0..143 ; chunk 1: rows 113..256 (outputs <144 dropped)
#pragma unroll
        for (int c0 = 0; c0 < 2; c0++) {
            int base = c0 ? 113 : 0;
            zero_acc();
            p3_loadA(base, 0, afr[0]);
            p3_loadB(0, bfr[0]);
#pragma unroll 2
            for (int kk = 0; kk < 144; kk += 16) {
                int cur = (kk >> 4) & 1, nx = cur ^ 1;
                if (kk + 16 < 144) { p3_loadA(base, kk + 16, afr[nx]); p3_loadB(kk + 16, bfr[nx]); }
                do_mmas(cur);
            }
            __syncthreads();   // all chunk GEMM reads of Zh done before writes

            const float inv = 1.0f / 256.0f;
#pragma unroll
            for (int mi = 0; mi < 3; mi++)
#pragma unroll
                for (int ni = 0; ni < 3; ni++)
#pragma unroll
                    for (int h = 0; h < 2; h++) {
                        float* cc = acc[mi][ni][h];
                        int row0 = wm + mi * 16 + g;
                        int col0 = wn + ni * 16 + h * 8 + 2 * t4;
#pragma unroll
                        for (int e = 0; e < 4; e++) {
                            int n = base + row0 + ((e >> 1) ? 8 : 0);
                            int j = col0 + (e & 1);
                            if (n < NP1 && j < DP1 && (c0 == 0 || n >= 144)) {
                                size_t fi = (size_t)n * DP1 + j;
                                float r = cc[e] * inv;
                                float a = __bfloat162float(Ac[n * AST + j]);
                                float zo = Zi[fi] + r + a;
                                Zo[fi] = zo;
                                Ac[n * AST + j] =
                                    __float2bfloat16(a + r * gml[fi]);
                                Zh[n * ZST + j] = __float2bfloat16(zo);
                            }
                        }
                    }
            __syncthreads();
        }
    }
}

// ------------------------------ kernel_launch -------------------------------
extern "C" void kernel_launch(void* const* d_in, const int* in_sizes, int n_in,
                              void* d_out, int out_size) {
    const float* Z        = (const float*)d_in[0];
    const float* allparam = (const float*)d_in[1];
    const float* gamma    = (const float*)d_in[2];

    const int smem_bytes = (257 * ZST + 2 * 144 * GST + 257 * AST) * (int)sizeof(bf16);
    cudaFuncSetAttribute(k_fused, cudaFuncAttributeMaxDynamicSharedMemorySize,
                         smem_bytes);

    k_convPQ<<<(NLAYER * 2 * 128 * 128 + 255) / 256, 256>>>(allparam);
    k_fused<<<BATCH, 288, smem_bytes>>>(Z, gamma, (float*)d_out);
}